// round 4
// baseline (speedup 1.0000x reference)
#include <cuda_runtime.h>
#include <math.h>
#include <stdint.h>

#define B 64
#define NPER 1024
#define NN (B*NPER)        // 65536 nodes
#define EPER (NPER*16)     // 16384 edges per graph
#define EE (B*EPER)        // 1048576 edges
#define H 128

// ---------------- scratch (device globals; no runtime allocation) ----------------
__device__ float g_h[NN*H];
__device__ float g_h2[NN*H];
__device__ float g_score[NN];
__device__ float g_fac[NN];
__device__ float g_nmask[NN];
__device__ float g_agg4[NN*4];
__device__ int   g_deg[NN];
__device__ int   g_off[NN];
__device__ int   g_srcs[EE];
__device__ float g_x123[B*2*H];
__device__ float g_inv[2];
__device__ uint32_t g_B2hi[256*128], g_B2lo[256*128];
__device__ uint32_t g_B3hi[256*128], g_B3lo[256*128];

// ---------------- tf32 helpers ----------------
__device__ __forceinline__ uint32_t f2tf(float a) {
    uint32_t r;
    asm("cvt.rna.tf32.f32 %0, %1;" : "=r"(r) : "f"(a));
    return r;
}
__device__ __forceinline__ void split_tf32(float a, uint32_t& hi, uint32_t& lo) {
    hi = f2tf(a);
    float rem = a - __uint_as_float(hi);
    lo = f2tf(rem);
}
__device__ __forceinline__ void mma_tf32(float* c, const uint32_t* a, const uint32_t* b) {
    asm volatile(
        "mma.sync.aligned.m16n8k8.row.col.f32.tf32.tf32.f32 "
        "{%0,%1,%2,%3},{%4,%5,%6,%7},{%8,%9},{%0,%1,%2,%3};"
        : "+f"(c[0]), "+f"(c[1]), "+f"(c[2]), "+f"(c[3])
        : "r"(a[0]), "r"(a[1]), "r"(a[2]), "r"(a[3]), "r"(b[0]), "r"(b[1]));
}

// ---------------- weight pre-split (both convs, one launch) ----------------
__global__ void k_prep(const float* __restrict__ w2r, const float* __restrict__ w2l,
                       const float* __restrict__ w3r, const float* __restrict__ w3l) {
    int blk = blockIdx.x;
    const float* Wr = (blk < 128) ? w2r : w3r;
    const float* Wl = (blk < 128) ? w2l : w3l;
    uint32_t* bhi = (blk < 128) ? g_B2hi : g_B3hi;
    uint32_t* blo = (blk < 128) ? g_B2lo : g_B3lo;
    int i = (blk & 127) * 256 + threadIdx.x;   // 32768 per conv
    int n = i >> 8, k = i & 255;
    float v = (k < 128) ? Wr[k * 128 + n] : Wl[(k - 128) * 128 + n];
    uint32_t hi, lo;
    split_tf32(v, hi, lo);
    bhi[i] = hi; blo[i] = lo;
}

// ---------------- both pool-weight norms, one launch ----------------
__global__ void k_norm2(const float* __restrict__ p1, const float* __restrict__ p2) {
    int w = threadIdx.x >> 5, lane = threadIdx.x & 31;  // 2 warps
    if (w > 1) return;
    const float* p = w ? p2 : p1;
    float s = 0.0f;
    #pragma unroll
    for (int i = 0; i < 4; i++) { float v = p[lane + i * 32]; s += v * v; }
    #pragma unroll
    for (int o = 16; o > 0; o >>= 1) s += __shfl_down_sync(0xffffffffu, s, o);
    if (lane == 0) g_inv[w] = 1.0f / sqrtf(s);
}

// ---------------- fused CSR build (dst cached in regs) ----------------
__global__ void __launch_bounds__(1024) k_build(const int* __restrict__ src,
                                                const int* __restrict__ dst) {
    __shared__ int cnt[NPER];
    __shared__ int s[NPER];
    int g = blockIdx.x, t = threadIdx.x;
    int e0 = g * EPER;
    int nbase = g * NPER;
    int dl[16];
    #pragma unroll
    for (int it = 0; it < 16; it++) dl[it] = dst[e0 + t + it * 1024] - nbase;
    cnt[t] = 0;
    __syncthreads();
    #pragma unroll
    for (int it = 0; it < 16; it++) atomicAdd(&cnt[dl[it]], 1);
    __syncthreads();
    int d = cnt[t];
    s[t] = d;
    __syncthreads();
    for (int off = 1; off < NPER; off <<= 1) {
        int v = (t >= off) ? s[t - off] : 0;
        __syncthreads();
        s[t] += v;
        __syncthreads();
    }
    int excl = s[t] - d;
    g_off[nbase + t] = e0 + excl;
    g_deg[nbase + t] = d;
    cnt[t] = excl;
    __syncthreads();
    #pragma unroll
    for (int it = 0; it < 16; it++) {
        int p = atomicAdd(&cnt[dl[it]], 1);
        g_srcs[e0 + p] = src[e0 + t + it * 1024];
    }
}

// ---------------- conv1: 4-wide aggregate + tiny GEMM + fused score ----------------
__global__ void k_agg4(const float* __restrict__ x) {
    int n = blockIdx.x * blockDim.x + threadIdx.x;
    if (n >= NN) return;
    int b0 = g_off[n], deg = g_deg[n];
    float4 acc = make_float4(0.f, 0.f, 0.f, 0.f);
    int e = b0, e4 = b0 + (deg & ~3);
    for (; e < e4; e += 4) {
        int s0 = g_srcs[e], s1 = g_srcs[e + 1], s2 = g_srcs[e + 2], s3 = g_srcs[e + 3];
        float4 v0 = *(const float4*)&x[s0 * 4];
        float4 v1 = *(const float4*)&x[s1 * 4];
        float4 v2 = *(const float4*)&x[s2 * 4];
        float4 v3 = *(const float4*)&x[s3 * 4];
        acc.x += v0.x + v1.x + v2.x + v3.x;
        acc.y += v0.y + v1.y + v2.y + v3.y;
        acc.z += v0.z + v1.z + v2.z + v3.z;
        acc.w += v0.w + v1.w + v2.w + v3.w;
    }
    for (; e < b0 + deg; e++) {
        int sidx = g_srcs[e];
        float4 v = *(const float4*)&x[sidx * 4];
        acc.x += v.x; acc.y += v.y; acc.z += v.z; acc.w += v.w;
    }
    *(float4*)&g_agg4[n * 4] = acc;
}

__global__ void k_conv1(const float* __restrict__ x, const float* __restrict__ w1r,
                        const float* __restrict__ b1, const float* __restrict__ w1l,
                        const float* __restrict__ p1w) {
    __shared__ float wr[4][H], wl[4][H], bb[H], pws[H];
    __shared__ float red[8];
    int t = threadIdx.x; // 256
    if (t < H) { bb[t] = b1[t]; pws[t] = p1w[t]; }
    for (int i = t; i < 4 * H; i += 256) { wr[i >> 7][i & 127] = w1r[i]; wl[i >> 7][i & 127] = w1l[i]; }
    __syncthreads();
    int n = blockIdx.x * 2 + (t >> 7);
    int o = t & 127;
    float4 a  = *(const float4*)&g_agg4[n * 4];
    float4 xv = *(const float4*)&x[n * 4];
    float v = bb[o]
            + a.x  * wr[0][o] + a.y  * wr[1][o] + a.z  * wr[2][o] + a.w  * wr[3][o]
            + xv.x * wl[0][o] + xv.y * wl[1][o] + xv.z * wl[2][o] + xv.w * wl[3][o];
    v = fmaxf(v, 0.0f);
    g_h[n * H + o] = v;
    float sv = v * pws[o];
    #pragma unroll
    for (int d = 16; d > 0; d >>= 1) sv += __shfl_down_sync(0xffffffffu, sv, d);
    int wid = t >> 5, lane = t & 31;
    if (lane == 0) red[wid] = sv;
    __syncthreads();
    if (t < 2)
        g_score[blockIdx.x * 2 + t] = red[t * 4] + red[t * 4 + 1] + red[t * 4 + 2] + red[t * 4 + 3];
}

// ---------------- rank by counting ----------------
__global__ void __launch_bounds__(256) k_rank(int k, int inv_idx) {
    __shared__ float s[NPER];
    int g = blockIdx.x >> 2, q = blockIdx.x & 3, t = threadIdx.x;
    for (int i = t; i < NPER; i += 256) s[i] = g_score[g * NPER + i];
    __syncthreads();
    int i = q * 256 + t;
    int node = g * NPER + i;
    float my = s[i];
    int cnt = 0;
    #pragma unroll 8
    for (int j = 0; j < NPER; j++) {
        float sj = s[j];
        cnt += (sj > my) || (sj == my && j < i);
    }
    bool keep = cnt < k;
    g_nmask[node] = keep ? 1.0f : 0.0f;
    g_fac[node]   = keep ? tanhf(my * g_inv[inv_idx]) : 0.0f;
}

// ---------------- readout ----------------
__global__ void __launch_bounds__(512) k_readout(const float* __restrict__ h, float invk, int accum) {
    __shared__ float smx[4][H], ssm[4][H];
    int g = blockIdx.x, t = threadIdx.x;
    int sub = t >> 7, f = t & 127;
    float mx = -INFINITY, sm = 0.0f;
    for (int n0 = sub; n0 < NPER; n0 += 4) {
        int node = g * NPER + n0;
        float fac = g_fac[node];
        float msk = g_nmask[node];
        float v = h[node * H + f] * fac;
        sm += v;
        if (msk > 0.0f) mx = fmaxf(mx, v);
    }
    smx[sub][f] = mx; ssm[sub][f] = sm;
    __syncthreads();
    if (sub == 0) {
        mx = fmaxf(fmaxf(smx[0][f], smx[1][f]), fmaxf(smx[2][f], smx[3][f]));
        sm = ssm[0][f] + ssm[1][f] + ssm[2][f] + ssm[3][f];
        if (accum) {
            g_x123[g * 2 * H + f]     += mx;
            g_x123[g * 2 * H + H + f] += sm * invk;
        } else {
            g_x123[g * 2 * H + f]     = mx;
            g_x123[g * 2 * H + H + f] = sm * invk;
        }
    }
}

// ---------------- fused gather + tensor-core conv + score epilogue ----------------
struct ConvSmem {
    float    AgT[128][260];   // [m][k] full K=256: 0..127 gathered, 128..255 self*f
    uint32_t Bh[2][128][36];  // double-buffered B hi [n][kc]
    uint32_t Bl[2][128][36];
    float    bs[128];
    float    pws[128];
    float    sc[128];
};

__global__ void __launch_bounds__(512, 1) k_conv_fused(
    const float* __restrict__ hin,
    const uint32_t* __restrict__ Bhi, const uint32_t* __restrict__ Blo,
    const float* __restrict__ bias, const float* __restrict__ pw,
    float* __restrict__ hout)
{
    extern __shared__ char smem_raw[];
    ConvSmem& S = *reinterpret_cast<ConvSmem*>(smem_raw);
    int tid = threadIdx.x;
    int m0 = blockIdx.x * 128;
    int wid = tid >> 5, lane = tid & 31;

    if (tid < 128) { S.bs[tid] = bias[tid]; S.pws[tid] = pw[tid]; S.sc[tid] = 0.0f; }

    // ---- gather half: AgT[m][0..127] = sum f[src]*h[src], 4x unrolled ----
    const float4* h4 = (const float4*)hin;
    #pragma unroll
    for (int i = 0; i < 8; i++) {
        int nl = wid * 8 + i;
        int n = m0 + nl;
        float4 acc = make_float4(0.f, 0.f, 0.f, 0.f);
        if (g_nmask[n] > 0.0f) {
            int b0 = g_off[n], deg = g_deg[n];
            int e = b0, e4 = b0 + (deg & ~3);
            for (; e < e4; e += 4) {
                int s0 = g_srcs[e], s1 = g_srcs[e + 1];
                int s2 = g_srcs[e + 2], s3 = g_srcs[e + 3];
                float f0 = g_fac[s0], f1 = g_fac[s1];
                float f2 = g_fac[s2], f3 = g_fac[s3];
                float4 v0 = h4[s0 * 32 + lane];
                float4 v1 = h4[s1 * 32 + lane];
                float4 v2 = h4[s2 * 32 + lane];
                float4 v3 = h4[s3 * 32 + lane];
                acc.x += f0 * v0.x + f1 * v1.x + f2 * v2.x + f3 * v3.x;
                acc.y += f0 * v0.y + f1 * v1.y + f2 * v2.y + f3 * v3.y;
                acc.z += f0 * v0.z + f1 * v1.z + f2 * v2.z + f3 * v3.z;
                acc.w += f0 * v0.w + f1 * v1.w + f2 * v2.w + f3 * v3.w;
            }
            for (; e < b0 + deg; e++) {
                int s = g_srcs[e];
                float fs = g_fac[s];
                float4 v = h4[s * 32 + lane];
                acc.x += fs * v.x; acc.y += fs * v.y;
                acc.z += fs * v.z; acc.w += fs * v.w;
            }
        }
        *(float4*)&S.AgT[nl][lane * 4] = acc;
    }

    // ---- self half: AgT[m][128..255] = f[m]*h[m] ----
    #pragma unroll
    for (int it = 0; it < 8; it++) {
        int j = tid + it * 512;           // 0..4095
        int r = j >> 5, c = (j & 31) * 4;
        float4 v = *(const float4*)&hin[(m0 + r) * 128 + c];
        float fm = g_fac[m0 + r];
        v.x *= fm; v.y *= fm; v.z *= fm; v.w *= fm;
        *(float4*)&S.AgT[r][128 + c] = v;
    }

    // ---- stage B chunk 0 ----
    #pragma unroll
    for (int it = 0; it < 2; it++) {
        int j = tid + it * 512;
        int n = j >> 3, c4 = (j & 7) * 4;
        *(uint4*)&S.Bh[0][n][c4] = *(const uint4*)&Bhi[n * 256 + c4];
        *(uint4*)&S.Bl[0][n][c4] = *(const uint4*)&Blo[n * 256 + c4];
    }
    __syncthreads();

    // ---- GEMM: 8 chunks of K=32, double-buffered B ----
    int wm = wid & 3, wn = wid >> 2;
    int grp = lane >> 2, tig = lane & 3;
    float acc[2][4][4];
    #pragma unroll
    for (int a = 0; a < 2; a++)
        #pragma unroll
        for (int b = 0; b < 4; b++)
            #pragma unroll
            for (int c = 0; c < 4; c++) acc[a][b][c] = 0.0f;

    for (int ko = 0; ko < 8; ko++) {
        if (ko < 7) {
            int nb = (ko + 1) & 1;
            #pragma unroll
            for (int it = 0; it < 2; it++) {
                int j = tid + it * 512;
                int n = j >> 3, c4 = (j & 7) * 4;
                *(uint4*)&S.Bh[nb][n][c4] = *(const uint4*)&Bhi[n * 256 + (ko + 1) * 32 + c4];
                *(uint4*)&S.Bl[nb][n][c4] = *(const uint4*)&Blo[n * 256 + (ko + 1) * 32 + c4];
            }
        }
        int buf = ko & 1;
        int kb = ko * 32;
        #pragma unroll
        for (int k8 = 0; k8 < 4; k8++) {
            int kk = kb + k8 * 8;
            uint32_t ahi[2][4], alo[2][4];
            #pragma unroll
            for (int mt = 0; mt < 2; mt++) {
                int mr = wm * 32 + mt * 16;
                float a0 = S.AgT[mr + grp][kk + tig];
                float a1 = S.AgT[mr + grp + 8][kk + tig];
                float a2 = S.AgT[mr + grp][kk + tig + 4];
                float a3 = S.AgT[mr + grp + 8][kk + tig + 4];
                split_tf32(a0, ahi[mt][0], alo[mt][0]);
                split_tf32(a1, ahi[mt][1], alo[mt][1]);
                split_tf32(a2, ahi[mt][2], alo[mt][2]);
                split_tf32(a3, ahi[mt][3], alo[mt][3]);
            }
            uint32_t bh[4][2], bl[4][2];
            #pragma unroll
            for (int nt = 0; nt < 4; nt++) {
                int nr = wn * 32 + nt * 8;
                int kq = k8 * 8;
                bh[nt][0] = S.Bh[buf][nr + grp][kq + tig];
                bh[nt][1] = S.Bh[buf][nr + grp][kq + tig + 4];
                bl[nt][0] = S.Bl[buf][nr + grp][kq + tig];
                bl[nt][1] = S.Bl[buf][nr + grp][kq + tig + 4];
            }
            #pragma unroll
            for (int mt = 0; mt < 2; mt++)
                #pragma unroll
                for (int nt = 0; nt < 4; nt++) {
                    mma_tf32(acc[mt][nt], ahi[mt], bh[nt]);
                    mma_tf32(acc[mt][nt], ahi[mt], bl[nt]);
                    mma_tf32(acc[mt][nt], alo[mt], bh[nt]);
                }
        }
        __syncthreads();
    }

    // ---- epilogue: bias + relu + nmask, write hout, fused score ----
    #pragma unroll
    for (int mt = 0; mt < 2; mt++) {
        int mrow = m0 + wm * 32 + mt * 16 + grp;
        float nm0 = g_nmask[mrow];
        float nm1 = g_nmask[mrow + 8];
        float dot0 = 0.0f, dot1 = 0.0f;
        #pragma unroll
        for (int nt = 0; nt < 4; nt++) {
            int n0 = wn * 32 + nt * 8 + tig * 2;
            float2 v0, v1;
            v0.x = fmaxf(acc[mt][nt][0] + S.bs[n0],     0.f) * nm0;
            v0.y = fmaxf(acc[mt][nt][1] + S.bs[n0 + 1], 0.f) * nm0;
            v1.x = fmaxf(acc[mt][nt][2] + S.bs[n0],     0.f) * nm1;
            v1.y = fmaxf(acc[mt][nt][3] + S.bs[n0 + 1], 0.f) * nm1;
            *(float2*)&hout[mrow * 128 + n0]       = v0;
            *(float2*)&hout[(mrow + 8) * 128 + n0] = v1;
            dot0 += v0.x * S.pws[n0] + v0.y * S.pws[n0 + 1];
            dot1 += v1.x * S.pws[n0] + v1.y * S.pws[n0 + 1];
        }
        dot0 += __shfl_xor_sync(0xffffffffu, dot0, 1, 4);
        dot0 += __shfl_xor_sync(0xffffffffu, dot0, 2, 4);
        dot1 += __shfl_xor_sync(0xffffffffu, dot1, 1, 4);
        dot1 += __shfl_xor_sync(0xffffffffu, dot1, 2, 4);
        if (tig == 0) {
            atomicAdd(&S.sc[wm * 32 + mt * 16 + grp],     dot0);
            atomicAdd(&S.sc[wm * 32 + mt * 16 + grp + 8], dot1);
        }
    }
    __syncthreads();
    if (tid < 128) {
        int m = m0 + tid;
        g_score[m] = (g_nmask[m] > 0.0f) ? S.sc[tid] : -INFINITY;
    }
}

// ---------------- final MLP + log_softmax ----------------
__global__ void k_mlp(const float* __restrict__ w1, const float* __restrict__ bb1,
                      const float* __restrict__ w2, const float* __restrict__ bb2,
                      const float* __restrict__ w3, const float* __restrict__ bb3,
                      float* __restrict__ out) {
    __shared__ float z[256], z1[H], z2[64], z3[7];
    int b = blockIdx.x, t = threadIdx.x; // 128 threads
    z[t]       = g_x123[b * 256 + t];
    z[t + 128] = g_x123[b * 256 + 128 + t];
    __syncthreads();
    float acc = bb1[t];
    for (int k = 0; k < 256; k++) acc += z[k] * w1[k * H + t];
    z1[t] = fmaxf(acc, 0.0f);
    __syncthreads();
    if (t < 64) {
        float a = bb2[t];
        for (int k = 0; k < H; k++) a += z1[k] * w2[k * 64 + t];
        z2[t] = fmaxf(a, 0.0f);
    }
    __syncthreads();
    if (t < 7) {
        float a = bb3[t];
        for (int k = 0; k < 64; k++) a += z2[k] * w3[k * 7 + t];
        z3[t] = a;
    }
    __syncthreads();
    if (t == 0) {
        float m = z3[0];
        for (int c = 1; c < 7; c++) m = fmaxf(m, z3[c]);
        float s = 0.0f;
        for (int c = 0; c < 7; c++) s += expf(z3[c] - m);
        float lse = logf(s);
        for (int c = 0; c < 7; c++) out[b * 7 + c] = z3[c] - m - lse;
    }
}

// ---------------- launch ----------------
extern "C" void kernel_launch(void* const* d_in, const int* in_sizes, int n_in,
                              void* d_out, int out_size) {
    (void)in_sizes; (void)n_in; (void)out_size;
    const float* x   = (const float*)d_in[0];
    const int*   ei  = (const int*)d_in[1];
    const int*   src = ei;
    const int*   dst = ei + EE;
    const float* w1r = (const float*)d_in[2];
    const float* b1  = (const float*)d_in[3];
    const float* w1l = (const float*)d_in[4];
    const float* w2r = (const float*)d_in[5];
    const float* b2  = (const float*)d_in[6];
    const float* w2l = (const float*)d_in[7];
    const float* w3r = (const float*)d_in[8];
    const float* b3  = (const float*)d_in[9];
    const float* w3l = (const float*)d_in[10];
    const float* p1w = (const float*)d_in[11];
    const float* p2w = (const float*)d_in[12];
    const float* wl1 = (const float*)d_in[13];
    const float* bl1 = (const float*)d_in[14];
    const float* wl2 = (const float*)d_in[15];
    const float* bl2 = (const float*)d_in[16];
    const float* wl3 = (const float*)d_in[17];
    const float* bl3 = (const float*)d_in[18];
    float* out = (float*)d_out;

    float *ph, *ph2;
    uint32_t *b2hi, *b2lo, *b3hi, *b3lo;
    cudaGetSymbolAddress((void**)&ph,   g_h);
    cudaGetSymbolAddress((void**)&ph2,  g_h2);
    cudaGetSymbolAddress((void**)&b2hi, g_B2hi);
    cudaGetSymbolAddress((void**)&b2lo, g_B2lo);
    cudaGetSymbolAddress((void**)&b3hi, g_B3hi);
    cudaGetSymbolAddress((void**)&b3lo, g_B3lo);

    static int smem_set = 0;
    if (!smem_set) {
        cudaFuncSetAttribute(k_conv_fused, cudaFuncAttributeMaxDynamicSharedMemorySize,
                             (int)sizeof(ConvSmem));
        smem_set = 1;
    }

    k_prep<<<256, 256>>>(w2r, w2l, w3r, w3l);
    k_norm2<<<1, 64>>>(p1w, p2w);
    k_build<<<B, 1024>>>(src, dst);

    // conv1 + score1
    k_agg4<<<NN / 256, 256>>>(x);
    k_conv1<<<NN / 2, 256>>>(x, w1r, b1, w1l, p1w);

    // pool1 (k=820) + readout1
    k_rank<<<B * 4, 256>>>(820, 0);
    k_readout<<<B, 512>>>(ph, 1.0f / 820.0f, 0);

    // conv2 (fused gather + gemm + score2)
    k_conv_fused<<<NN / 128, 512, sizeof(ConvSmem)>>>(ph, b2hi, b2lo, b2, p2w, ph2);

    // pool2 (k=656) + readout2
    k_rank<<<B * 4, 256>>>(656, 1);
    k_readout<<<B, 512>>>(ph2, 1.0f / 656.0f, 1);

    // conv3 (fused, scores with p2w again)
    k_conv_fused<<<NN / 128, 512, sizeof(ConvSmem)>>>(ph2, b3hi, b3lo, b3, p2w, ph);

    // pool3 (k=525) + readout3
    k_rank<<<B * 4, 256>>>(525, 1);
    k_readout<<<B, 512>>>(ph, 1.0f / 525.0f, 1);

    // head
    k_mlp<<<B, 128>>>(wl1, bl1, wl2, bl2, wl3, bl3, out);
}

// round 5
// speedup vs baseline: 1.4690x; 1.4690x over previous
#include <cuda_runtime.h>
#include <math.h>
#include <stdint.h>

#define B 64
#define NPER 1024
#define NN (B*NPER)        // 65536 nodes
#define EPER (NPER*16)     // 16384 edges per graph
#define EE (B*EPER)        // 1048576 edges
#define H 128

// ---------------- scratch (device globals; no runtime allocation) ----------------
__device__ float g_h[NN*H];
__device__ float g_h2[NN*H];
__device__ float g_score[NN];
__device__ float g_fac[NN];
__device__ float g_nmask[NN];
__device__ float g_agg4[NN*4];
__device__ int   g_deg[NN];
__device__ int   g_off[NN];
__device__ int   g_srcs[EE];
__device__ float g_x123[B*2*H];
__device__ float g_inv[2];
__device__ uint32_t g_B2hi[256*128], g_B2lo[256*128];
__device__ uint32_t g_B3hi[256*128], g_B3lo[256*128];

// ---------------- tf32 helpers ----------------
__device__ __forceinline__ uint32_t f2tf(float a) {
    uint32_t r;
    asm("cvt.rna.tf32.f32 %0, %1;" : "=r"(r) : "f"(a));
    return r;
}
__device__ __forceinline__ void split_tf32(float a, uint32_t& hi, uint32_t& lo) {
    hi = f2tf(a);
    float rem = a - __uint_as_float(hi);
    lo = f2tf(rem);
}
__device__ __forceinline__ void mma_tf32(float* c, const uint32_t* a, const uint32_t* b) {
    asm volatile(
        "mma.sync.aligned.m16n8k8.row.col.f32.tf32.tf32.f32 "
        "{%0,%1,%2,%3},{%4,%5,%6,%7},{%8,%9},{%0,%1,%2,%3};"
        : "+f"(c[0]), "+f"(c[1]), "+f"(c[2]), "+f"(c[3])
        : "r"(a[0]), "r"(a[1]), "r"(a[2]), "r"(a[3]), "r"(b[0]), "r"(b[1]));
}

// ---------------- weight pre-split (both convs, one launch) ----------------
__global__ void k_prep(const float* __restrict__ w2r, const float* __restrict__ w2l,
                       const float* __restrict__ w3r, const float* __restrict__ w3l) {
    int blk = blockIdx.x;
    const float* Wr = (blk < 128) ? w2r : w3r;
    const float* Wl = (blk < 128) ? w2l : w3l;
    uint32_t* bhi = (blk < 128) ? g_B2hi : g_B3hi;
    uint32_t* blo = (blk < 128) ? g_B2lo : g_B3lo;
    int i = (blk & 127) * 256 + threadIdx.x;   // 32768 per conv
    int n = i >> 8, k = i & 255;
    float v = (k < 128) ? Wr[k * 128 + n] : Wl[(k - 128) * 128 + n];
    uint32_t hi, lo;
    split_tf32(v, hi, lo);
    bhi[i] = hi; blo[i] = lo;
}

// ---------------- both pool-weight norms, one launch ----------------
__global__ void k_norm2(const float* __restrict__ p1, const float* __restrict__ p2) {
    int w = threadIdx.x >> 5, lane = threadIdx.x & 31;  // 2 warps
    if (w > 1) return;
    const float* p = w ? p2 : p1;
    float s = 0.0f;
    #pragma unroll
    for (int i = 0; i < 4; i++) { float v = p[lane + i * 32]; s += v * v; }
    #pragma unroll
    for (int o = 16; o > 0; o >>= 1) s += __shfl_down_sync(0xffffffffu, s, o);
    if (lane == 0) g_inv[w] = 1.0f / sqrtf(s);
}

// ---------------- fused CSR build (dst cached in regs) ----------------
__global__ void __launch_bounds__(1024) k_build(const int* __restrict__ src,
                                                const int* __restrict__ dst) {
    __shared__ int cnt[NPER];
    __shared__ int s[NPER];
    int g = blockIdx.x, t = threadIdx.x;
    int e0 = g * EPER;
    int nbase = g * NPER;
    int dl[16];
    #pragma unroll
    for (int it = 0; it < 16; it++) dl[it] = dst[e0 + t + it * 1024] - nbase;
    cnt[t] = 0;
    __syncthreads();
    #pragma unroll
    for (int it = 0; it < 16; it++) atomicAdd(&cnt[dl[it]], 1);
    __syncthreads();
    int d = cnt[t];
    s[t] = d;
    __syncthreads();
    for (int off = 1; off < NPER; off <<= 1) {
        int v = (t >= off) ? s[t - off] : 0;
        __syncthreads();
        s[t] += v;
        __syncthreads();
    }
    int excl = s[t] - d;
    g_off[nbase + t] = e0 + excl;
    g_deg[nbase + t] = d;
    cnt[t] = excl;
    __syncthreads();
    #pragma unroll
    for (int it = 0; it < 16; it++) {
        int p = atomicAdd(&cnt[dl[it]], 1);
        g_srcs[e0 + p] = src[e0 + t + it * 1024];
    }
}

// ---------------- conv1: 4-wide aggregate + tiny GEMM + fused score ----------------
__global__ void k_agg4(const float* __restrict__ x) {
    int n = blockIdx.x * blockDim.x + threadIdx.x;
    if (n >= NN) return;
    int b0 = g_off[n], e0 = b0 + g_deg[n];
    float4 acc = make_float4(0.f, 0.f, 0.f, 0.f);
    for (int e = b0; e < e0; e++) {
        int sidx = g_srcs[e];
        float4 v = *(const float4*)&x[sidx * 4];
        acc.x += v.x; acc.y += v.y; acc.z += v.z; acc.w += v.w;
    }
    *(float4*)&g_agg4[n * 4] = acc;
}

__global__ void k_conv1(const float* __restrict__ x, const float* __restrict__ w1r,
                        const float* __restrict__ b1, const float* __restrict__ w1l,
                        const float* __restrict__ p1w) {
    __shared__ float wr[4][H], wl[4][H], bb[H], pws[H];
    __shared__ float red[8];
    int t = threadIdx.x; // 256
    if (t < H) { bb[t] = b1[t]; pws[t] = p1w[t]; }
    for (int i = t; i < 4 * H; i += 256) { wr[i >> 7][i & 127] = w1r[i]; wl[i >> 7][i & 127] = w1l[i]; }
    __syncthreads();
    int n = blockIdx.x * 2 + (t >> 7);
    int o = t & 127;
    float4 a  = *(const float4*)&g_agg4[n * 4];
    float4 xv = *(const float4*)&x[n * 4];
    float v = bb[o]
            + a.x  * wr[0][o] + a.y  * wr[1][o] + a.z  * wr[2][o] + a.w  * wr[3][o]
            + xv.x * wl[0][o] + xv.y * wl[1][o] + xv.z * wl[2][o] + xv.w * wl[3][o];
    v = fmaxf(v, 0.0f);
    g_h[n * H + o] = v;
    float sv = v * pws[o];
    #pragma unroll
    for (int d = 16; d > 0; d >>= 1) sv += __shfl_down_sync(0xffffffffu, sv, d);
    int wid = t >> 5, lane = t & 31;
    if (lane == 0) red[wid] = sv;
    __syncthreads();
    if (t < 2)
        g_score[blockIdx.x * 2 + t] = red[t * 4] + red[t * 4 + 1] + red[t * 4 + 2] + red[t * 4 + 3];
}

// ---------------- rank by counting ----------------
__global__ void __launch_bounds__(256) k_rank(int k, int inv_idx) {
    __shared__ float s[NPER];
    int g = blockIdx.x >> 2, q = blockIdx.x & 3, t = threadIdx.x;
    for (int i = t; i < NPER; i += 256) s[i] = g_score[g * NPER + i];
    __syncthreads();
    int i = q * 256 + t;
    int node = g * NPER + i;
    float my = s[i];
    int cnt = 0;
    #pragma unroll 8
    for (int j = 0; j < NPER; j++) {
        float sj = s[j];
        cnt += (sj > my) || (sj == my && j < i);
    }
    bool keep = cnt < k;
    g_nmask[node] = keep ? 1.0f : 0.0f;
    g_fac[node]   = keep ? tanhf(my * g_inv[inv_idx]) : 0.0f;
}

// ---------------- readout ----------------
__global__ void __launch_bounds__(512) k_readout(const float* __restrict__ h, float invk, int accum) {
    __shared__ float smx[4][H], ssm[4][H];
    int g = blockIdx.x, t = threadIdx.x;
    int sub = t >> 7, f = t & 127;
    float mx = -INFINITY, sm = 0.0f;
    for (int n0 = sub; n0 < NPER; n0 += 4) {
        int node = g * NPER + n0;
        float fac = g_fac[node];
        float msk = g_nmask[node];
        float v = h[node * H + f] * fac;
        sm += v;
        if (msk > 0.0f) mx = fmaxf(mx, v);
    }
    smx[sub][f] = mx; ssm[sub][f] = sm;
    __syncthreads();
    if (sub == 0) {
        mx = fmaxf(fmaxf(smx[0][f], smx[1][f]), fmaxf(smx[2][f], smx[3][f]));
        sm = ssm[0][f] + ssm[1][f] + ssm[2][f] + ssm[3][f];
        if (accum) {
            g_x123[g * 2 * H + f]     += mx;
            g_x123[g * 2 * H + H + f] += sm * invk;
        } else {
            g_x123[g * 2 * H + f]     = mx;
            g_x123[g * 2 * H + H + f] = sm * invk;
        }
    }
}

// ---------------- fused gather + tensor-core conv + score epilogue (R2 structure) ----------------
struct ConvSmem {
    float    AgT[128][132];   // gathered agg [m][k]
    float    As2[128][36];    // self chunk [m][kc]
    uint32_t Bhs[128][36];    // B hi [n][kc]
    uint32_t Bls[128][36];    // B lo [n][kc]
    float    bs[128];
    float    pws[128];
    float    sc[128];
};

__global__ void __launch_bounds__(512, 1) k_conv_fused(
    const float* __restrict__ hin,
    const uint32_t* __restrict__ Bhi, const uint32_t* __restrict__ Blo,
    const float* __restrict__ bias, const float* __restrict__ pw,
    float* __restrict__ hout)
{
    extern __shared__ char smem_raw[];
    ConvSmem& S = *reinterpret_cast<ConvSmem*>(smem_raw);
    int tid = threadIdx.x;
    int m0 = blockIdx.x * 128;
    int wid = tid >> 5, lane = tid & 31;

    if (tid < 128) { S.bs[tid] = bias[tid]; S.pws[tid] = pw[tid]; S.sc[tid] = 0.0f; }

    // ---- phase 1: gather agg into AgT[m][k], batched index/fac loads, skip dead srcs ----
    const float4* h4 = (const float4*)hin;
    #pragma unroll
    for (int i = 0; i < 8; i++) {
        int nl = wid * 8 + i;
        int n = m0 + nl;
        float4 acc = make_float4(0.f, 0.f, 0.f, 0.f);
        if (g_nmask[n] > 0.0f) {
            int b0 = g_off[n], deg = g_deg[n];
            int e = b0, e4 = b0 + (deg & ~3);
            for (; e < e4; e += 4) {
                int s0 = g_srcs[e],     s1 = g_srcs[e + 1];
                int s2 = g_srcs[e + 2], s3 = g_srcs[e + 3];
                float f0 = g_fac[s0], f1 = g_fac[s1];
                float f2 = g_fac[s2], f3 = g_fac[s3];
                if (f0 != 0.0f) {
                    float4 v = h4[s0 * 32 + lane];
                    acc.x += f0 * v.x; acc.y += f0 * v.y; acc.z += f0 * v.z; acc.w += f0 * v.w;
                }
                if (f1 != 0.0f) {
                    float4 v = h4[s1 * 32 + lane];
                    acc.x += f1 * v.x; acc.y += f1 * v.y; acc.z += f1 * v.z; acc.w += f1 * v.w;
                }
                if (f2 != 0.0f) {
                    float4 v = h4[s2 * 32 + lane];
                    acc.x += f2 * v.x; acc.y += f2 * v.y; acc.z += f2 * v.z; acc.w += f2 * v.w;
                }
                if (f3 != 0.0f) {
                    float4 v = h4[s3 * 32 + lane];
                    acc.x += f3 * v.x; acc.y += f3 * v.y; acc.z += f3 * v.z; acc.w += f3 * v.w;
                }
            }
            for (; e < b0 + deg; e++) {
                int s = g_srcs[e];
                float fs = g_fac[s];
                if (fs != 0.0f) {
                    float4 v = h4[s * 32 + lane];
                    acc.x += fs * v.x; acc.y += fs * v.y;
                    acc.z += fs * v.z; acc.w += fs * v.w;
                }
            }
        }
        *(float4*)&S.AgT[nl][lane * 4] = acc;
    }
    __syncthreads();

    // ---- phase 2: GEMM K=256 (4 chunks from AgT, 4 chunks self from global) ----
    int wm = wid & 3, wn = wid >> 2;
    int grp = lane >> 2, tig = lane & 3;
    float acc[2][4][4];
    #pragma unroll
    for (int a = 0; a < 2; a++)
        #pragma unroll
        for (int b = 0; b < 4; b++)
            #pragma unroll
            for (int c = 0; c < 4; c++) acc[a][b][c] = 0.0f;

    for (int ko = 0; ko < 8; ko++) {
        // stage B chunk (pre-split, pre-transposed [n][256])
        #pragma unroll
        for (int it = 0; it < 2; it++) {
            int j = tid + it * 512;
            int n = j >> 3, c4 = (j & 7) * 4;
            *(uint4*)&S.Bhs[n][c4] = *(const uint4*)&Bhi[n * 256 + ko * 32 + c4];
            *(uint4*)&S.Bls[n][c4] = *(const uint4*)&Blo[n * 256 + ko * 32 + c4];
        }
        if (ko >= 4) {
            #pragma unroll
            for (int it = 0; it < 2; it++) {
                int j = tid + it * 512;
                int r = j >> 3, c4 = (j & 7) * 4;
                float4 v = *(const float4*)&hin[(m0 + r) * 128 + (ko - 4) * 32 + c4];
                float fm = g_fac[m0 + r];
                v.x *= fm; v.y *= fm; v.z *= fm; v.w *= fm;
                *(float4*)&S.As2[r][c4] = v;
            }
        }
        __syncthreads();
        bool self = (ko >= 4);
        int kb = ko * 32;
        #pragma unroll
        for (int k8 = 0; k8 < 4; k8++) {
            int kk = k8 * 8;
            uint32_t ahi[2][4], alo[2][4];
            #pragma unroll
            for (int mt = 0; mt < 2; mt++) {
                int mr = wm * 32 + mt * 16;
                float a0, a1, a2, a3;
                if (!self) {
                    a0 = S.AgT[mr + grp][kb + kk + tig];
                    a1 = S.AgT[mr + grp + 8][kb + kk + tig];
                    a2 = S.AgT[mr + grp][kb + kk + tig + 4];
                    a3 = S.AgT[mr + grp + 8][kb + kk + tig + 4];
                } else {
                    a0 = S.As2[mr + grp][kk + tig];
                    a1 = S.As2[mr + grp + 8][kk + tig];
                    a2 = S.As2[mr + grp][kk + tig + 4];
                    a3 = S.As2[mr + grp + 8][kk + tig + 4];
                }
                split_tf32(a0, ahi[mt][0], alo[mt][0]);
                split_tf32(a1, ahi[mt][1], alo[mt][1]);
                split_tf32(a2, ahi[mt][2], alo[mt][2]);
                split_tf32(a3, ahi[mt][3], alo[mt][3]);
            }
            uint32_t bh[4][2], bl[4][2];
            #pragma unroll
            for (int nt = 0; nt < 4; nt++) {
                int nr = wn * 32 + nt * 8;
                bh[nt][0] = S.Bhs[nr + grp][kk + tig];
                bh[nt][1] = S.Bhs[nr + grp][kk + tig + 4];
                bl[nt][0] = S.Bls[nr + grp][kk + tig];
                bl[nt][1] = S.Bls[nr + grp][kk + tig + 4];
            }
            #pragma unroll
            for (int mt = 0; mt < 2; mt++)
                #pragma unroll
                for (int nt = 0; nt < 4; nt++) {
                    mma_tf32(acc[mt][nt], ahi[mt], bh[nt]);
                    mma_tf32(acc[mt][nt], ahi[mt], bl[nt]);
                    mma_tf32(acc[mt][nt], alo[mt], bh[nt]);
                }
        }
        __syncthreads();
    }

    // ---- phase 3: epilogue (bias+relu+nmask, write hout, fused score) ----
    #pragma unroll
    for (int mt = 0; mt < 2; mt++) {
        int mrow = m0 + wm * 32 + mt * 16 + grp;
        float nm0 = g_nmask[mrow];
        float nm1 = g_nmask[mrow + 8];
        float dot0 = 0.0f, dot1 = 0.0f;
        #pragma unroll
        for (int nt = 0; nt < 4; nt++) {
            int n0 = wn * 32 + nt * 8 + tig * 2;
            float2 v0, v1;
            v0.x = fmaxf(acc[mt][nt][0] + S.bs[n0],     0.f) * nm0;
            v0.y = fmaxf(acc[mt][nt][1] + S.bs[n0 + 1], 0.f) * nm0;
            v1.x = fmaxf(acc[mt][nt][2] + S.bs[n0],     0.f) * nm1;
            v1.y = fmaxf(acc[mt][nt][3] + S.bs[n0 + 1], 0.f) * nm1;
            *(float2*)&hout[mrow * 128 + n0]       = v0;
            *(float2*)&hout[(mrow + 8) * 128 + n0] = v1;
            dot0 += v0.x * S.pws[n0] + v0.y * S.pws[n0 + 1];
            dot1 += v1.x * S.pws[n0] + v1.y * S.pws[n0 + 1];
        }
        dot0 += __shfl_xor_sync(0xffffffffu, dot0, 1, 4);
        dot0 += __shfl_xor_sync(0xffffffffu, dot0, 2, 4);
        dot1 += __shfl_xor_sync(0xffffffffu, dot1, 1, 4);
        dot1 += __shfl_xor_sync(0xffffffffu, dot1, 2, 4);
        if (tig == 0) {
            atomicAdd(&S.sc[wm * 32 + mt * 16 + grp],     dot0);
            atomicAdd(&S.sc[wm * 32 + mt * 16 + grp + 8], dot1);
        }
    }
    __syncthreads();
    if (tid < 128) {
        int m = m0 + tid;
        g_score[m] = (g_nmask[m] > 0.0f) ? S.sc[tid] : -INFINITY;
    }
}

// ---------------- final MLP + log_softmax ----------------
__global__ void k_mlp(const float* __restrict__ w1, const float* __restrict__ bb1,
                      const float* __restrict__ w2, const float* __restrict__ bb2,
                      const float* __restrict__ w3, const float* __restrict__ bb3,
                      float* __restrict__ out) {
    __shared__ float z[256], z1[H], z2[64], z3[7];
    int b = blockIdx.x, t = threadIdx.x; // 128 threads
    z[t]       = g_x123[b * 256 + t];
    z[t + 128] = g_x123[b * 256 + 128 + t];
    __syncthreads();
    float acc = bb1[t];
    for (int k = 0; k < 256; k++) acc += z[k] * w1[k * H + t];
    z1[t] = fmaxf(acc, 0.0f);
    __syncthreads();
    if (t < 64) {
        float a = bb2[t];
        for (int k = 0; k < H; k++) a += z1[k] * w2[k * 64 + t];
        z2[t] = fmaxf(a, 0.0f);
    }
    __syncthreads();
    if (t < 7) {
        float a = bb3[t];
        for (int k = 0; k < 64; k++) a += z2[k] * w3[k * 7 + t];
        z3[t] = a;
    }
    __syncthreads();
    if (t == 0) {
        float m = z3[0];
        for (int c = 1; c < 7; c++) m = fmaxf(m, z3[c]);
        float s = 0.0f;
        for (int c = 0; c < 7; c++) s += expf(z3[c] - m);
        float lse = logf(s);
        for (int c = 0; c < 7; c++) out[b * 7 + c] = z3[c] - m - lse;
    }
}

// ---------------- launch ----------------
extern "C" void kernel_launch(void* const* d_in, const int* in_sizes, int n_in,
                              void* d_out, int out_size) {
    (void)in_sizes; (void)n_in; (void)out_size;
    const float* x   = (const float*)d_in[0];
    const int*   ei  = (const int*)d_in[1];
    const int*   src = ei;
    const int*   dst = ei + EE;
    const float* w1r = (const float*)d_in[2];
    const float* b1  = (const float*)d_in[3];
    const float* w1l = (const float*)d_in[4];
    const float* w2r = (const float*)d_in[5];
    const float* b2  = (const float*)d_in[6];
    const float* w2l = (const float*)d_in[7];
    const float* w3r = (const float*)d_in[8];
    const float* b3  = (const float*)d_in[9];
    const float* w3l = (const float*)d_in[10];
    const float* p1w = (const float*)d_in[11];
    const float* p2w = (const float*)d_in[12];
    const float* wl1 = (const float*)d_in[13];
    const float* bl1 = (const float*)d_in[14];
    const float* wl2 = (const float*)d_in[15];
    const float* bl2 = (const float*)d_in[16];
    const float* wl3 = (const float*)d_in[17];
    const float* bl3 = (const float*)d_in[18];
    float* out = (float*)d_out;

    float *ph, *ph2;
    uint32_t *b2hi, *b2lo, *b3hi, *b3lo;
    cudaGetSymbolAddress((void**)&ph,   g_h);
    cudaGetSymbolAddress((void**)&ph2,  g_h2);
    cudaGetSymbolAddress((void**)&b2hi, g_B2hi);
    cudaGetSymbolAddress((void**)&b2lo, g_B2lo);
    cudaGetSymbolAddress((void**)&b3hi, g_B3hi);
    cudaGetSymbolAddress((void**)&b3lo, g_B3lo);

    static int smem_set = 0;
    if (!smem_set) {
        cudaFuncSetAttribute(k_conv_fused, cudaFuncAttributeMaxDynamicSharedMemorySize,
                             (int)sizeof(ConvSmem));
        smem_set = 1;
    }

    k_prep<<<256, 256>>>(w2r, w2l, w3r, w3l);
    k_norm2<<<1, 64>>>(p1w, p2w);
    k_build<<<B, 1024>>>(src, dst);

    // conv1 + score1
    k_agg4<<<NN / 256, 256>>>(x);
    k_conv1<<<NN / 2, 256>>>(x, w1r, b1, w1l, p1w);

    // pool1 (k=820) + readout1
    k_rank<<<B * 4, 256>>>(820, 0);
    k_readout<<<B, 512>>>(ph, 1.0f / 820.0f, 0);

    // conv2 (fused gather + gemm + score2)
    k_conv_fused<<<NN / 128, 512, sizeof(ConvSmem)>>>(ph, b2hi, b2lo, b2, p2w, ph2);

    // pool2 (k=656) + readout2
    k_rank<<<B * 4, 256>>>(656, 1);
    k_readout<<<B, 512>>>(ph2, 1.0f / 656.0f, 1);

    // conv3 (fused, scores with p2w again)
    k_conv_fused<<<NN / 128, 512, sizeof(ConvSmem)>>>(ph2, b3hi, b3lo, b3, p2w, ph);

    // pool3 (k=525) + readout3
    k_rank<<<B * 4, 256>>>(525, 1);
    k_readout<<<B, 512>>>(ph, 1.0f / 525.0f, 1);

    // head
    k_mlp<<<B, 128>>>(wl1, bl1, wl2, bl2, wl3, bl3, out);
}